// round 7
// baseline (speedup 1.0000x reference)
#include <cuda_runtime.h>

// out[r] = (sum over 1024 elems of row r of x) * (sum of coeffs)
// x: (16, 4096, 1024) fp32 -> 65536 rows of 1024
// coeffs: (10, 1) fp32
//
// One warp per TWO adjacent rows (8KB contiguous). All 16 float4 loads
// are independent and front-batched -> 64 x 128B lines in flight per warp.
// Both row-sums reduced together with one packed-double butterfly.

__global__ __launch_bounds__(256) void spline_rowsum2_kernel(
    const float* __restrict__ x,
    const float* __restrict__ coeffs,
    int n_coeffs,
    float* __restrict__ out,
    int npairs)
{
    int gwarp = (blockIdx.x * blockDim.x + threadIdx.x) >> 5;
    int lane  = threadIdx.x & 31;
    if (gwarp >= npairs) return;

    const float4* p = reinterpret_cast<const float4*>(x) + (size_t)gwarp * 512;

    // Row A: 8 independent loads
    float4 a0 = p[lane +   0];
    float4 a1 = p[lane +  32];
    float4 a2 = p[lane +  64];
    float4 a3 = p[lane +  96];
    float4 a4 = p[lane + 128];
    float4 a5 = p[lane + 160];
    float4 a6 = p[lane + 192];
    float4 a7 = p[lane + 224];
    // Row B: 8 independent loads
    float4 b0 = p[lane + 256];
    float4 b1 = p[lane + 288];
    float4 b2 = p[lane + 320];
    float4 b3 = p[lane + 352];
    float4 b4 = p[lane + 384];
    float4 b5 = p[lane + 416];
    float4 b6 = p[lane + 448];
    float4 b7 = p[lane + 480];

    float sa = (((a0.x + a0.y) + (a0.z + a0.w)) + ((a1.x + a1.y) + (a1.z + a1.w)))
             + (((a2.x + a2.y) + (a2.z + a2.w)) + ((a3.x + a3.y) + (a3.z + a3.w)))
             + (((a4.x + a4.y) + (a4.z + a4.w)) + ((a5.x + a5.y) + (a5.z + a5.w)))
             + (((a6.x + a6.y) + (a6.z + a6.w)) + ((a7.x + a7.y) + (a7.z + a7.w)));
    float sb = (((b0.x + b0.y) + (b0.z + b0.w)) + ((b1.x + b1.y) + (b1.z + b1.w)))
             + (((b2.x + b2.y) + (b2.z + b2.w)) + ((b3.x + b3.y) + (b3.z + b3.w)))
             + (((b4.x + b4.y) + (b4.z + b4.w)) + ((b5.x + b5.y) + (b5.z + b5.w)))
             + (((b6.x + b6.y) + (b6.z + b6.w)) + ((b7.x + b7.y) + (b7.z + b7.w)));

    // Packed butterfly: reduce both rows with 5 shuffles (8B each)
    float2 sv = make_float2(sa, sb);
    unsigned long long pk = *reinterpret_cast<unsigned long long*>(&sv);
#pragma unroll
    for (int off = 16; off; off >>= 1) {
        unsigned long long other = __shfl_xor_sync(0xFFFFFFFFu, pk, off);
        float2 o = *reinterpret_cast<float2*>(&other);
        float2 s = *reinterpret_cast<float2*>(&pk);
        s.x += o.x; s.y += o.y;
        pk = *reinterpret_cast<unsigned long long*>(&s);
    }
    float2 tot = *reinterpret_cast<float2*>(&pk);

    if (lane == 0) {
        float c = 0.0f;
        for (int i = 0; i < n_coeffs; i++) c += coeffs[i];
        out[2 * gwarp]     = tot.x * c;
        out[2 * gwarp + 1] = tot.y * c;
    }
}

extern "C" void kernel_launch(void* const* d_in, const int* in_sizes, int n_in,
                              void* d_out, int out_size)
{
    const float* x      = (const float*)d_in[0];
    const float* coeffs = (const float*)d_in[1];
    float* out          = (float*)d_out;

    int nrows    = in_sizes[0] / 1024;   // 65536
    int n_coeffs = in_sizes[1];          // 10
    int npairs   = nrows / 2;            // 32768

    // 8 warps (16 rows) per 256-thread block
    int blocks = (npairs + 7) / 8;       // 4096
    spline_rowsum2_kernel<<<blocks, 256>>>(x, coeffs, n_coeffs, out, npairs);
}

// round 9
// speedup vs baseline: 1.0548x; 1.0548x over previous
#include <cuda_runtime.h>

// out[r] = (sum over 1024 elems of row r of x) * (sum of coeffs)
// x: (16, 4096, 1024) fp32 -> 65536 rows of 1024
// coeffs: (10, 1) fp32
//
// R0 shape: one warp per row, fire-and-exit. Loads are 256-bit
// (v8.b32) with L2::evict_first — zero-reuse stream. 4 loads/lane x 32B
// = 128B/lane, warp covers the 4KB row.

__device__ __forceinline__ void ldg256_ef(const float* p, float* v) {
    asm volatile(
        "ld.global.nc.L2::evict_first.v8.b32 {%0,%1,%2,%3,%4,%5,%6,%7}, [%8];"
        : "=f"(v[0]), "=f"(v[1]), "=f"(v[2]), "=f"(v[3]),
          "=f"(v[4]), "=f"(v[5]), "=f"(v[6]), "=f"(v[7])
        : "l"(p));
}

__global__ __launch_bounds__(256) void spline_rowsum_v8_kernel(
    const float* __restrict__ x,
    const float* __restrict__ coeffs,
    int n_coeffs,
    float* __restrict__ out,
    int nrows)
{
    int gwarp = (blockIdx.x * blockDim.x + threadIdx.x) >> 5;
    int lane  = threadIdx.x & 31;
    if (gwarp >= nrows) return;

    // row base in floats; each lane handles 8 floats (32B) per load,
    // 4 independent loads strided 1024 floats? No: stride 256 floats
    // (one warp-load = 32 lanes * 8 floats = 256 floats = 1KB).
    const float* row = x + (size_t)gwarp * 1024 + lane * 8;

    float v0[8], v1[8], v2[8], v3[8];
    ldg256_ef(row +   0, v0);
    ldg256_ef(row + 256, v1);
    ldg256_ef(row + 512, v2);
    ldg256_ef(row + 768, v3);

    float s0 = ((v0[0] + v0[1]) + (v0[2] + v0[3])) + ((v0[4] + v0[5]) + (v0[6] + v0[7]));
    float s1 = ((v1[0] + v1[1]) + (v1[2] + v1[3])) + ((v1[4] + v1[5]) + (v1[6] + v1[7]));
    float s2 = ((v2[0] + v2[1]) + (v2[2] + v2[3])) + ((v2[4] + v2[5]) + (v2[6] + v2[7]));
    float s3 = ((v3[0] + v3[1]) + (v3[2] + v3[3])) + ((v3[4] + v3[5]) + (v3[6] + v3[7]));
    float s = (s0 + s1) + (s2 + s3);

    // butterfly warp reduction
#pragma unroll
    for (int off = 16; off; off >>= 1)
        s += __shfl_xor_sync(0xFFFFFFFFu, s, off);

    if (lane == 0) {
        float c = 0.0f;
        for (int i = 0; i < n_coeffs; i++) c += coeffs[i];
        out[gwarp] = s * c;
    }
}

extern "C" void kernel_launch(void* const* d_in, const int* in_sizes, int n_in,
                              void* d_out, int out_size)
{
    const float* x      = (const float*)d_in[0];
    const float* coeffs = (const float*)d_in[1];
    float* out          = (float*)d_out;

    int nrows    = in_sizes[0] / 1024;   // 65536
    int n_coeffs = in_sizes[1];          // 10

    // 8 warps (rows) per 256-thread block — R0 launch shape
    int blocks = (nrows + 7) / 8;        // 8192
    spline_rowsum_v8_kernel<<<blocks, 256>>>(x, coeffs, n_coeffs, out, nrows);
}

// round 10
// speedup vs baseline: 1.0556x; 1.0008x over previous
#include <cuda_runtime.h>

// out[r] = (sum over 1024 elems of row r of x) * (sum of coeffs)
// x: (16, 4096, 1024) fp32 -> 65536 rows of 1024
// coeffs: (10, 1) fp32
//
// One warp per row, fire-and-exit. All four 256-bit evict_first loads are
// emitted in a SINGLE asm block with 32 distinct output registers, forcing
// ptxas to keep every load in flight (guaranteed per-lane MLP=4x32B)
// before any arithmetic consumes them.

__global__ __launch_bounds__(256) void spline_rowsum_v8mlp_kernel(
    const float* __restrict__ x,
    const float* __restrict__ coeffs,
    int n_coeffs,
    float* __restrict__ out,
    int nrows)
{
    int gwarp = (blockIdx.x * blockDim.x + threadIdx.x) >> 5;
    int lane  = threadIdx.x & 31;
    if (gwarp >= nrows) return;

    const float* row = x + (size_t)gwarp * 1024 + lane * 8;

    float f0, f1, f2, f3, f4, f5, f6, f7,
          f8, f9, f10, f11, f12, f13, f14, f15,
          f16, f17, f18, f19, f20, f21, f22, f23,
          f24, f25, f26, f27, f28, f29, f30, f31;

    // 4 x 256-bit loads, one asm block -> 32 live dest regs, all issued
    // back-to-back. Offsets in bytes: 256 floats = 1024B apart.
    asm volatile(
        "ld.global.nc.L2::evict_first.v8.b32 {%0,%1,%2,%3,%4,%5,%6,%7}, [%32];\n\t"
        "ld.global.nc.L2::evict_first.v8.b32 {%8,%9,%10,%11,%12,%13,%14,%15}, [%32+1024];\n\t"
        "ld.global.nc.L2::evict_first.v8.b32 {%16,%17,%18,%19,%20,%21,%22,%23}, [%32+2048];\n\t"
        "ld.global.nc.L2::evict_first.v8.b32 {%24,%25,%26,%27,%28,%29,%30,%31}, [%32+3072];"
        : "=f"(f0),  "=f"(f1),  "=f"(f2),  "=f"(f3),
          "=f"(f4),  "=f"(f5),  "=f"(f6),  "=f"(f7),
          "=f"(f8),  "=f"(f9),  "=f"(f10), "=f"(f11),
          "=f"(f12), "=f"(f13), "=f"(f14), "=f"(f15),
          "=f"(f16), "=f"(f17), "=f"(f18), "=f"(f19),
          "=f"(f20), "=f"(f21), "=f"(f22), "=f"(f23),
          "=f"(f24), "=f"(f25), "=f"(f26), "=f"(f27),
          "=f"(f28), "=f"(f29), "=f"(f30), "=f"(f31)
        : "l"(row));

    float s0 = ((f0  + f1)  + (f2  + f3))  + ((f4  + f5)  + (f6  + f7));
    float s1 = ((f8  + f9)  + (f10 + f11)) + ((f12 + f13) + (f14 + f15));
    float s2 = ((f16 + f17) + (f18 + f19)) + ((f20 + f21) + (f22 + f23));
    float s3 = ((f24 + f25) + (f26 + f27)) + ((f28 + f29) + (f30 + f31));
    float s = (s0 + s1) + (s2 + s3);

    // butterfly warp reduction
#pragma unroll
    for (int off = 16; off; off >>= 1)
        s += __shfl_xor_sync(0xFFFFFFFFu, s, off);

    if (lane == 0) {
        float c = 0.0f;
        for (int i = 0; i < n_coeffs; i++) c += coeffs[i];
        out[gwarp] = s * c;
    }
}

extern "C" void kernel_launch(void* const* d_in, const int* in_sizes, int n_in,
                              void* d_out, int out_size)
{
    const float* x      = (const float*)d_in[0];
    const float* coeffs = (const float*)d_in[1];
    float* out          = (float*)d_out;

    int nrows    = in_sizes[0] / 1024;   // 65536
    int n_coeffs = in_sizes[1];          // 10

    // 8 warps (rows) per 256-thread block
    int blocks = (nrows + 7) / 8;        // 8192
    spline_rowsum_v8mlp_kernel<<<blocks, 256>>>(x, coeffs, n_coeffs, out, nrows);
}